// round 3
// baseline (speedup 1.0000x reference)
#include <cuda_runtime.h>

// ===================== Problem constants =====================
// M=3, N=8, G=8, K=3
// x: (32, 3, 224, 224) f32   w: (24, 1, 3, 3) f32
// out: (32, 192, 222, 222) f32, group conv: out channel o uses in channel o/64
// o = mn*8 + g  (mn in [0,24), g in [0,8)), group m = mn/8 -> channels [64m, 64m+64) contiguous.

#define IMG 224
#define OUT 222
#define NCH 192
#define PLANE_OUT (OUT*OUT)        // 49284

// duplicated rotated weights: (w,w) packed as u64, layout [192][9]
__device__ unsigned long long g_rotw2[192 * 9];

typedef unsigned long long u64;

__device__ __forceinline__ u64 ffma2(u64 a, u64 b, u64 c) {
    u64 d;
    asm("fma.rn.f32x2 %0, %1, %2, %3;" : "=l"(d) : "l"(a), "l"(b), "l"(c));
    return d;
}
__device__ __forceinline__ u64 pack2(float lo, float hi) {
    u64 d;
    asm("mov.b64 %0, {%1, %2};" : "=l"(d) : "f"(lo), "f"(hi));
    return d;
}
__device__ __forceinline__ void unpack2(u64 v, float& lo, float& hi) {
    asm("mov.b64 {%0, %1}, %2;" : "=f"(lo), "=f"(hi) : "l"(v));
}

// ===================== Kernel 1: rotate weights =====================
// rot[g][mn][h][w] = bilinear sample of w[mn] at rotated coords (zero pad).
// Writes duplicated pairs (v,v) to g_rotw2[(mn*8+g)*9 + h*3 + w].
__global__ void rotw_kernel(const float* __restrict__ w) {
    int t = blockIdx.x * blockDim.x + threadIdx.x;
    if (t >= 192 * 9) return;
    int o  = t / 9, j = t % 9;
    int mn = o >> 3, g = o & 7;
    int hh = j / 3, ww = j % 3;

    // angle: linspace(-90, 90, 8)[g] in degrees -> radians (float64, like numpy)
    double ang = (-90.0 + (180.0 / 7.0) * (double)g) * 0.017453292519943295;
    float c = (float)cos(ang);
    float s = (float)sin(ang);

    // coords[k] = (2k+1)/3 - 1 ;  base = (coords[w], coords[h], 1)
    float cx = (2.0f * ww + 1.0f) / 3.0f - 1.0f;
    float cy = (2.0f * hh + 1.0f) / 3.0f - 1.0f;
    float gx = c * cx - s * cy;
    float gy = s * cx + c * cy;

    float ix = ((gx + 1.0f) * 3.0f - 1.0f) * 0.5f;
    float iy = ((gy + 1.0f) * 3.0f - 1.0f) * 0.5f;
    float x0f = floorf(ix), y0f = floorf(iy);
    int   x0  = (int)x0f,   y0  = (int)y0f;
    float wx1 = ix - x0f, wy1 = iy - y0f;
    float wx0 = 1.0f - wx1, wy0 = 1.0f - wy1;

    const float* wp = w + mn * 9;   // w is (24,1,3,3)
    float v00 = 0.f, v10 = 0.f, v01 = 0.f, v11 = 0.f;
    int x1 = x0 + 1, y1 = y0 + 1;
    bool bx0 = (x0 >= 0 && x0 < 3), bx1 = (x1 >= 0 && x1 < 3);
    bool by0 = (y0 >= 0 && y0 < 3), by1 = (y1 >= 0 && y1 < 3);
    if (bx0 && by0) v00 = wp[y0 * 3 + x0];
    if (bx1 && by0) v10 = wp[y0 * 3 + x1];
    if (bx0 && by1) v01 = wp[y1 * 3 + x0];
    if (bx1 && by1) v11 = wp[y1 * 3 + x1];

    float v = v00 * (wx0 * wy0) + v10 * (wx1 * wy0)
            + v01 * (wx0 * wy1) + v11 * (wx1 * wy1);

    g_rotw2[t] = pack2(v, v);
}

// ===================== Kernel 2: grouped conv =====================
// CTA: one (n, m) plane, 64-wide x 32-tall output tile, all 64 channels of group m.
// Thread: 2 output cols x 4 output rows, packed f32x2 math, STG.64 stores.
#define TW 64
#define TH 32
#define RR 4
#define IN_W 66
#define IN_H 34

__global__ void __launch_bounds__(256)
conv_kernel(const float* __restrict__ x, float* __restrict__ out) {
    __shared__ __align__(16) float s_in[IN_H * IN_W];
    __shared__ __align__(16) u64   s_w[64 * 9];

    int nm  = blockIdx.z;          // n*3 + m
    int m   = nm % 3;
    int tx0 = blockIdx.x * TW;
    int ty0 = blockIdx.y * TH;
    int tid = threadIdx.x;

    // input plane for (n, m): x is (32,3,224,224) -> plane index nm
    const float* xp = x + (size_t)nm * (IMG * IMG);

    // cooperative load of input tile (clamped; clamped junk only feeds invalid outputs)
    for (int i = tid; i < IN_H * IN_W; i += 256) {
        int r  = i / IN_W, cc = i % IN_W;
        int gr = ty0 + r;  if (gr > IMG - 1) gr = IMG - 1;
        int gc = tx0 + cc; if (gc > IMG - 1) gc = IMG - 1;
        s_in[i] = xp[gr * IMG + gc];
    }
    // weights for this group (already duplicated pairs)
    {
        const u64* gw = g_rotw2 + m * 64 * 9;
        for (int i = tid; i < 64 * 9; i += 256) s_w[i] = gw[i];
    }
    __syncthreads();

    int tcol = tid & 31;           // 0..31
    int trow = tid >> 5;           // 0..7
    int lx = 2 * tcol;             // local col (even)
    int ly = RR * trow;            // local row
    int ox = tx0 + lx;
    int oy = ty0 + ly;
    // 222 even + ox even => pair (ox, ox+1) fully valid iff ox < 222
    if (ox >= OUT || oy >= OUT) return;
    bool rv1 = (oy + 1) < OUT;
    bool rv2 = (oy + 2) < OUT;
    bool rv3 = (oy + 3) < OUT;

    // register-load input pairs: rows ly..ly+5, 3 overlapping pairs per row
    u64 ip[6][3];
#pragma unroll
    for (int r = 0; r < 6; r++) {
        const u64* p = (const u64*)&s_in[(ly + r) * IN_W + lx];  // 8B aligned
        u64 a = p[0], b = p[1];
        float a0, a1, a2, a3;
        unpack2(a, a0, a1);
        unpack2(b, a2, a3);
        ip[r][0] = a;
        ip[r][1] = pack2(a1, a2);
        ip[r][2] = b;
    }

    int n = nm / 3;
    float* outp = out + (size_t)(n * NCH + m * 64) * PLANE_OUT
                      + (size_t)oy * OUT + ox;

    for (int c = 0; c < 64; c++) {
        u64 wv[9];
#pragma unroll
        for (int j = 0; j < 9; j++) wv[j] = s_w[c * 9 + j];

        u64 acc0 = 0, acc1 = 0, acc2 = 0, acc3 = 0;
#pragma unroll
        for (int dy = 0; dy < 3; dy++) {
#pragma unroll
            for (int dx = 0; dx < 3; dx++) {
                u64 wt = wv[dy * 3 + dx];
                acc0 = ffma2(ip[0 + dy][dx], wt, acc0);
                acc1 = ffma2(ip[1 + dy][dx], wt, acc1);
                acc2 = ffma2(ip[2 + dy][dx], wt, acc2);
                acc3 = ffma2(ip[3 + dy][dx], wt, acc3);
            }
        }
        *(u64*)(outp)                 = acc0;
        if (rv1) *(u64*)(outp + OUT)     = acc1;
        if (rv2) *(u64*)(outp + 2 * OUT) = acc2;
        if (rv3) *(u64*)(outp + 3 * OUT) = acc3;
        outp += PLANE_OUT;
    }
}

// ===================== launch =====================
extern "C" void kernel_launch(void* const* d_in, const int* in_sizes, int n_in,
                              void* d_out, int out_size) {
    const float* x = (const float*)d_in[0];
    const float* w = (const float*)d_in[1];
    float* out = (float*)d_out;

    rotw_kernel<<<7, 256>>>(w);

    dim3 grid((OUT + TW - 1) / TW,   // 4
              (OUT + TH - 1) / TH,   // 7
              32 * 3);               // 96
    conv_kernel<<<grid, 256>>>(x, out);
}